// round 8
// baseline (speedup 1.0000x reference)
#include <cuda_runtime.h>

#define BB 32
#define NN 128
#define DD 64
#define HH 128
#define NROWS (BB*NN)   // 4096

// ---------------- scratch (device globals) ----------------
__device__ float g_AI[BB*NN*HH];   // x @ A1[:d]
__device__ float g_AJ[BB*NN*HH];   // x @ A1[d:] + ab1
__device__ float g_WI[BB*NN*HH];   // x @ W1[:d]
__device__ float g_WJ[BB*NN*HH];   // x @ W1[d:] + b1

// ---------------- per-node projections: 16 rows/block, direct weight reads ----------------
__global__ __launch_bounds__(256, 2)
void proj_kernel(const float* __restrict__ x,
                 const float* __restrict__ A1, const float* __restrict__ W1,
                 const float* __restrict__ b1, const float* __restrict__ ab1) {
    __shared__ __align__(16) float4 xr[16*16];   // 16 rows x 64 cols
    int t = threadIdx.x;
    int col = t & 127;
    int half = t >> 7;
    int row0 = blockIdx.x * 16;
    xr[t] = ((const float4*)x)[row0*16 + t];
    __syncthreads();
    float biasAJ = ab1[col];
    float biasWJ = b1[col];
    float a0[8], a1[8], a2[8], a3[8];
    #pragma unroll
    for (int r = 0; r < 8; ++r) { a0[r]=0.f; a1[r]=0.f; a2[r]=0.f; a3[r]=0.f; }
    #pragma unroll 2
    for (int d4 = 0; d4 < 16; ++d4) {
        float w0x = A1[(d4*4+0)*HH + col], w0y = A1[(d4*4+1)*HH + col];
        float w0z = A1[(d4*4+2)*HH + col], w0w = A1[(d4*4+3)*HH + col];
        float w1x = A1[(64+d4*4+0)*HH + col], w1y = A1[(64+d4*4+1)*HH + col];
        float w1z = A1[(64+d4*4+2)*HH + col], w1w = A1[(64+d4*4+3)*HH + col];
        float w2x = W1[(d4*4+0)*HH + col], w2y = W1[(d4*4+1)*HH + col];
        float w2z = W1[(d4*4+2)*HH + col], w2w = W1[(d4*4+3)*HH + col];
        float w3x = W1[(64+d4*4+0)*HH + col], w3y = W1[(64+d4*4+1)*HH + col];
        float w3z = W1[(64+d4*4+2)*HH + col], w3w = W1[(64+d4*4+3)*HH + col];
        #pragma unroll
        for (int r = 0; r < 8; ++r) {
            float4 xv = xr[(half*8 + r)*16 + d4];   // broadcast LDS
            a0[r] += xv.x*w0x + xv.y*w0y + xv.z*w0z + xv.w*w0w;
            a1[r] += xv.x*w1x + xv.y*w1y + xv.z*w1z + xv.w*w1w;
            a2[r] += xv.x*w2x + xv.y*w2y + xv.z*w2z + xv.w*w2w;
            a3[r] += xv.x*w3x + xv.y*w3y + xv.z*w3z + xv.w*w3w;
        }
    }
    #pragma unroll
    for (int r = 0; r < 8; ++r) {
        int row = row0 + half*8 + r;
        g_AI[row*HH + col] = a0[r];
        g_AJ[row*HH + col] = a1[r] + biasAJ;
        g_WI[row*HH + col] = a2[r];
        g_WJ[row*HH + col] = a3[r] + biasWJ;
    }
}

// ---------------- fused pair + update kernel: 512 threads, full table ----------------
// 256 blocks (32 b x 8 i-tiles of 16), 512 threads, 2 blocks/SM -> single wave.
// SMEM floats:
//   tab : [0, 16512)       [j=128][h=128] stride 129 (AJ, then WJ);
//                          after pass2: xr[0..1024) aggs[1024..3072) us[3072..5120)
//   hsb : [16512, 18560)   pass1 aiT [h][16]  ->  pass2 output hs [r=16][128]
//   attn: [18560, 20608)   [j][16]
//   a2s : [20608, 20736)
//   red : [20736, 20864)   [quad][warpInQuad][4] x {max, sum}
//   msk : [20864, 20992)   ints
#define SMF_FLOATS 20992
#define SMEM_FUSED (SMF_FLOATS * 4)
__global__ __launch_bounds__(512, 2)
void fused_kernel(const float* __restrict__ x, const float* __restrict__ A2,
                  const int* __restrict__ masks,
                  const float* __restrict__ W2, const float* __restrict__ b2,
                  const float* __restrict__ U1, const float* __restrict__ ub1,
                  const float* __restrict__ U2, const float* __restrict__ ub2,
                  float* __restrict__ out) {
    extern __shared__ __align__(16) float sm[];
    float* tab  = sm;
    float* hsb  = sm + 16512;   // aiT during pass1, hs after pass2
    float* attn = sm + 18560;
    float* a2s  = sm + 20608;
    float* red  = sm + 20736;
    int*   msk  = (int*)(sm + 20864);

    int t = threadIdx.x;
    int c128 = t & 127;
    int quad = t >> 7;          // 0..3
    int lane = t & 31;
    int wq = (t >> 5) & 3;      // warp within quad
    int b  = blockIdx.x >> 3;
    int i0 = (blockIdx.x & 7) * 16;
    int rowbase = b*NN + i0;

    // preload x tile into registers (16 rows x 64 = 1024 floats)
    float xreg0 = x[rowbase*DD + t];
    float xreg1 = x[rowbase*DD + 512 + t];

    if (t < 128) { a2s[t] = A2[t]; msk[t] = masks[b*NN + t]; }

    // full AJ table: tab[j][h], stride 129
    const float* AJb = g_AJ + b*NN*HH;
    #pragma unroll
    for (int it = 0; it < 32; ++it) {
        int idx = it*512 + t;
        int j = idx >> 7, h = idx & 127;
        tab[j*129 + h] = AJb[j*HH + h];
    }
    // aiT[h=c128][ii] for this quad's 4 i's
    const float* AIb = g_AI + rowbase*HH;
    #pragma unroll
    for (int k = 0; k < 4; ++k)
        hsb[c128*16 + quad*4 + k] = AIb[(quad*4 + k)*HH + c128];

    int cnt = __syncthreads_count(msk[c128] != 0);
    float sa = (cnt > 0) ? 1.0f : 0.0f;
    bool mj = msk[c128] != 0;

    // ---- PASS 1: logits; thread = (j=c128, quad: 4 i's) ----
    float l[4];
    #pragma unroll
    for (int k = 0; k < 4; ++k) l[k] = 0.f;
    {
        const float* tp = tab + c128*129;
        const float* sp = hsb + quad*4;
        #pragma unroll 4
        for (int h = 0; h < HH; ++h) {
            float av  = tp[h];
            float a2v = a2s[h];
            float4 sv = *(const float4*)(sp + h*16);   // broadcast LDS.128
            l[0] = fmaf(fmaxf(av + sv.x, 0.f), a2v, l[0]);
            l[1] = fmaf(fmaxf(av + sv.y, 0.f), a2v, l[1]);
            l[2] = fmaf(fmaxf(av + sv.z, 0.f), a2v, l[2]);
            l[3] = fmaf(fmaxf(av + sv.w, 0.f), a2v, l[3]);
        }
    }
    if (!mj) {
        #pragma unroll
        for (int k = 0; k < 4; ++k) l[k] = -1e30f;
    }
    // reduce over j within each quad (4 warps cover 128 j)
    {
        #pragma unroll
        for (int k = 0; k < 4; ++k) {
            float v = l[k];
            #pragma unroll
            for (int off = 16; off; off >>= 1) v = fmaxf(v, __shfl_xor_sync(0xffffffffu, v, off));
            if (lane == 0) red[quad*16 + wq*4 + k] = v;
        }
    }
    __syncthreads();
    float e[4];
    {
        const float* rb = red + quad*16;
        #pragma unroll
        for (int k = 0; k < 4; ++k) {
            float mm = fmaxf(fmaxf(rb[k], rb[4+k]), fmaxf(rb[8+k], rb[12+k]));
            e[k] = mj ? __expf(l[k] - mm) : 0.f;
        }
        #pragma unroll
        for (int k = 0; k < 4; ++k) {
            float v = e[k];
            #pragma unroll
            for (int off = 16; off; off >>= 1) v += __shfl_xor_sync(0xffffffffu, v, off);
            if (lane == 0) red[64 + quad*16 + wq*4 + k] = v;
        }
    }
    __syncthreads();
    {
        const float* rb = red + 64 + quad*16;
        #pragma unroll
        for (int k = 0; k < 4; ++k) {
            float ss = rb[k] + rb[4+k] + rb[8+k] + rb[12+k];
            float inv = (cnt > 0) ? (1.0f / ss) : 0.f;
            attn[c128*16 + quad*4 + k] = e[k] * inv;
        }
    }
    __syncthreads();   // attn done; AJ table reads done

    // ---- reload table with WJ ----
    const float* WJb = g_WJ + b*NN*HH;
    #pragma unroll
    for (int it = 0; it < 32; ++it) {
        int idx = it*512 + t;
        int j = idx >> 7, h = idx & 127;
        tab[j*129 + h] = WJb[j*HH + h];
    }
    __syncthreads();

    // ---- PASS 2: weighted hidden sum; thread = (h=c128, quad: 4 i's) ----
    {
        const float* WIb = g_WI + rowbase*HH;
        float wi0 = WIb[(quad*4    )*HH + c128];
        float wi1 = WIb[(quad*4 + 1)*HH + c128];
        float wi2 = WIb[(quad*4 + 2)*HH + c128];
        float wi3 = WIb[(quad*4 + 3)*HH + c128];
        float h0 = 0.f, h1 = 0.f, h2 = 0.f, h3 = 0.f;
        const float* tp = tab + c128;
        const float* ap = attn + quad*4;
        #pragma unroll 4
        for (int j = 0; j < NN; ++j) {
            float wv = tp[j*129];
            float4 at = *(const float4*)(ap + j*16);   // broadcast LDS.128
            h0 = fmaf(at.x, fmaxf(wi0 + wv, 0.f), h0);
            h1 = fmaf(at.y, fmaxf(wi1 + wv, 0.f), h1);
            h2 = fmaf(at.z, fmaxf(wi2 + wv, 0.f), h2);
            h3 = fmaf(at.w, fmaxf(wi3 + wv, 0.f), h3);
        }
        hsb[(quad*4    )*128 + c128] = h0;
        hsb[(quad*4 + 1)*128 + c128] = h1;
        hsb[(quad*4 + 2)*128 + c128] = h2;
        hsb[(quad*4 + 3)*128 + c128] = h3;
    }
    __syncthreads();   // hs complete; tab free

    // ---- UPDATE phases (overlay xr/aggs/us onto tab) ----
    float* xr   = tab;          // 1024 floats [r=16][64]
    float* aggs = tab + 1024;   // 2048 floats [r][128]
    float* us   = tab + 3072;   // 2048 floats [r][128]

    xr[t] = xreg0;
    xr[512 + t] = xreg1;

    // Phase A: agg[r][col] = hs[r] @ W2[:,col] + b2[col]*sa   (4 rows/thread)
    {
        float b2v = b2[c128];
        float acc[4];
        #pragma unroll
        for (int k = 0; k < 4; ++k) acc[k] = b2v * sa;
        const float4* hs4 = (const float4*)hsb;
        #pragma unroll 4
        for (int h4 = 0; h4 < 32; ++h4) {
            float wx = W2[(h4*4+0)*HH + c128];
            float wy = W2[(h4*4+1)*HH + c128];
            float wz = W2[(h4*4+2)*HH + c128];
            float ww = W2[(h4*4+3)*HH + c128];
            #pragma unroll
            for (int k = 0; k < 4; ++k) {
                float4 hv = hs4[(quad*4 + k)*32 + h4];   // broadcast LDS
                acc[k] += hv.x*wx + hv.y*wy + hv.z*wz + hv.w*ww;
            }
        }
        #pragma unroll
        for (int k = 0; k < 4; ++k) aggs[(quad*4 + k)*128 + c128] = acc[k];
    }
    __syncthreads();

    // Phase B: us[r][col] = relu([x_r, agg_r] @ U1[:,col] + ub1[col])
    {
        float ubv = ub1[c128];
        float u[4];
        #pragma unroll
        for (int k = 0; k < 4; ++k) u[k] = ubv;
        const float4* xr4 = (const float4*)xr;
        const float4* ag4 = (const float4*)aggs;
        #pragma unroll 4
        for (int c4 = 0; c4 < 48; ++c4) {
            float wx = U1[(c4*4+0)*HH + c128];
            float wy = U1[(c4*4+1)*HH + c128];
            float wz = U1[(c4*4+2)*HH + c128];
            float ww = U1[(c4*4+3)*HH + c128];
            #pragma unroll
            for (int k = 0; k < 4; ++k) {
                int r = quad*4 + k;
                float4 cv = (c4 < 16) ? xr4[r*16 + c4] : ag4[r*32 + (c4-16)];
                u[k] += cv.x*wx + cv.y*wy + cv.z*wz + cv.w*ww;
            }
        }
        #pragma unroll
        for (int k = 0; k < 4; ++k) us[(quad*4 + k)*128 + c128] = fmaxf(u[k], 0.f);
    }
    __syncthreads();

    // Phase C: out[r][col] = x[r][col] + us[r] @ U2[:,col] + ub2[col]  (2 rows/thread)
    {
        int col = t & 63;
        int rg  = t >> 6;            // 0..7 -> rows rg*2, rg*2+1
        float ub2v = ub2[col];
        float o0 = ub2v, o1 = ub2v;
        const float4* us4 = (const float4*)us;
        #pragma unroll 4
        for (int k4 = 0; k4 < 32; ++k4) {
            float wx = U2[(k4*4+0)*DD + col];
            float wy = U2[(k4*4+1)*DD + col];
            float wz = U2[(k4*4+2)*DD + col];
            float ww = U2[(k4*4+3)*DD + col];
            float4 u0 = us4[(rg*2    )*32 + k4];   // broadcast
            float4 u1 = us4[(rg*2 + 1)*32 + k4];
            o0 += u0.x*wx + u0.y*wy + u0.z*wz + u0.w*ww;
            o1 += u1.x*wx + u1.y*wy + u1.z*wz + u1.w*ww;
        }
        int r0 = rg*2;
        out[(rowbase + r0    )*DD + col] = xr[r0*64 + col] + o0;
        out[(rowbase + r0 + 1)*DD + col] = xr[(r0+1)*64 + col] + o1;
    }
}

// ---------------- launch ----------------
extern "C" void kernel_launch(void* const* d_in, const int* in_sizes, int n_in,
                              void* d_out, int out_size) {
    const float* x    = (const float*)d_in[0];
    const int*   masks= (const int*)  d_in[1];
    const float* W1   = (const float*)d_in[2];
    const float* b1   = (const float*)d_in[3];
    const float* W2   = (const float*)d_in[4];
    const float* b2   = (const float*)d_in[5];
    const float* A1   = (const float*)d_in[6];
    const float* ab1  = (const float*)d_in[7];
    const float* A2   = (const float*)d_in[8];
    // d_in[9] = ab2: cancels in softmax
    const float* U1   = (const float*)d_in[10];
    const float* ub1  = (const float*)d_in[11];
    const float* U2   = (const float*)d_in[12];
    const float* ub2  = (const float*)d_in[13];
    float* out = (float*)d_out;

    cudaFuncSetAttribute(fused_kernel, cudaFuncAttributeMaxDynamicSharedMemorySize, SMEM_FUSED);

    proj_kernel<<<NROWS/16, 256>>>(x, A1, W1, b1, ab1);
    fused_kernel<<<BB*8, 512, SMEM_FUSED>>>(x, A2, masks, W2, b2, U1, ub1, U2, ub2, out);
}

// round 9
// speedup vs baseline: 1.1716x; 1.1716x over previous
#include <cuda_runtime.h>

#define BB 32
#define NN 128
#define DD 64
#define HH 128
#define NROWS (BB*NN)   // 4096

// ---------------- scratch (device globals) ----------------
__device__ float g_AI[BB*NN*HH];   // x @ A1[:d]
__device__ float g_AJ[BB*NN*HH];   // x @ A1[d:] + ab1
__device__ float g_WI[BB*NN*HH];   // x @ W1[:d]
__device__ float g_WJ[BB*NN*HH];   // x @ W1[d:] + b1

// ---------------- per-node projections: 16 rows/block, direct weight reads ----------------
__global__ __launch_bounds__(256, 2)
void proj_kernel(const float* __restrict__ x,
                 const float* __restrict__ A1, const float* __restrict__ W1,
                 const float* __restrict__ b1, const float* __restrict__ ab1) {
    __shared__ __align__(16) float4 xr[16*16];   // 16 rows x 64 cols
    int t = threadIdx.x;
    int col = t & 127;
    int half = t >> 7;
    int row0 = blockIdx.x * 16;
    xr[t] = ((const float4*)x)[row0*16 + t];
    __syncthreads();
    float biasAJ = ab1[col];
    float biasWJ = b1[col];
    float a0[8], a1[8], a2[8], a3[8];
    #pragma unroll
    for (int r = 0; r < 8; ++r) { a0[r]=0.f; a1[r]=0.f; a2[r]=0.f; a3[r]=0.f; }
    #pragma unroll 2
    for (int d4 = 0; d4 < 16; ++d4) {
        float w0x = A1[(d4*4+0)*HH + col], w0y = A1[(d4*4+1)*HH + col];
        float w0z = A1[(d4*4+2)*HH + col], w0w = A1[(d4*4+3)*HH + col];
        float w1x = A1[(64+d4*4+0)*HH + col], w1y = A1[(64+d4*4+1)*HH + col];
        float w1z = A1[(64+d4*4+2)*HH + col], w1w = A1[(64+d4*4+3)*HH + col];
        float w2x = W1[(d4*4+0)*HH + col], w2y = W1[(d4*4+1)*HH + col];
        float w2z = W1[(d4*4+2)*HH + col], w2w = W1[(d4*4+3)*HH + col];
        float w3x = W1[(64+d4*4+0)*HH + col], w3y = W1[(64+d4*4+1)*HH + col];
        float w3z = W1[(64+d4*4+2)*HH + col], w3w = W1[(64+d4*4+3)*HH + col];
        #pragma unroll
        for (int r = 0; r < 8; ++r) {
            float4 xv = xr[(half*8 + r)*16 + d4];   // broadcast LDS
            a0[r] += xv.x*w0x + xv.y*w0y + xv.z*w0z + xv.w*w0w;
            a1[r] += xv.x*w1x + xv.y*w1y + xv.z*w1z + xv.w*w1w;
            a2[r] += xv.x*w2x + xv.y*w2y + xv.z*w2z + xv.w*w2w;
            a3[r] += xv.x*w3x + xv.y*w3y + xv.z*w3z + xv.w*w3w;
        }
    }
    #pragma unroll
    for (int r = 0; r < 8; ++r) {
        int row = row0 + half*8 + r;
        g_AI[row*HH + col] = a0[r];
        g_AJ[row*HH + col] = a1[r] + biasAJ;
        g_WI[row*HH + col] = a2[r];
        g_WJ[row*HH + col] = a3[r] + biasWJ;
    }
}

// ---------------- fused pair + update kernel: 256 threads, full 128-h table ----------------
// 256 blocks (32 b x 8 i-tiles of 16), 256 threads, 84KB smem -> 2 blocks/SM.
// SMEM floats:
//   tab : [0, 16512)       [j=128][h=128] stride 129 (AJ, then WJ);
//                          after pass2: xr[0..1024) aggs[1024..3072) us[3072..5120)
//   hsb : [16512, 18560)   pass1 aiT [h][16]  ->  pass2 output hs [r=16][128]
//   attn: [18560, 20608)   [j][16]
//   a2s : [20608, 20736)
//   red : [20736, 20864)   [half][wq][8] x {max, sum}
//   msk : [20864, 20992)   ints
#define SMF_FLOATS 20992
#define SMEM_FUSED (SMF_FLOATS * 4)
__global__ __launch_bounds__(256, 2)
void fused_kernel(const float* __restrict__ x, const float* __restrict__ A2,
                  const int* __restrict__ masks,
                  const float* __restrict__ W2, const float* __restrict__ b2,
                  const float* __restrict__ U1, const float* __restrict__ ub1,
                  const float* __restrict__ U2, const float* __restrict__ ub2,
                  float* __restrict__ out) {
    extern __shared__ __align__(16) float sm[];
    float* tab  = sm;
    float* hsb  = sm + 16512;   // aiT during pass1, hs after pass2
    float* attn = sm + 18560;
    float* a2s  = sm + 20608;
    float* red  = sm + 20736;
    int*   msk  = (int*)(sm + 20864);

    int t = threadIdx.x;
    int c128 = t & 127;
    int half = t >> 7;          // 0/1 -> 8 i's each
    int lane = t & 31;
    int wq = (t >> 5) & 3;      // warp within half
    int b  = blockIdx.x >> 3;
    int i0 = (blockIdx.x & 7) * 16;
    int rowbase = b*NN + i0;

    // preload x tile into registers (16 rows x 64 = 1024 floats)
    float xreg[4];
    #pragma unroll
    for (int k = 0; k < 4; ++k) xreg[k] = x[rowbase*DD + k*256 + t];

    if (t < 128) { a2s[t] = A2[t]; msk[t] = masks[b*NN + t]; }

    // full AJ table: tab[j][h], stride 129 (each thread: 64 elems)
    const float* AJb = g_AJ + b*NN*HH;
    #pragma unroll 8
    for (int it = 0; it < 64; ++it) {
        int idx = it*256 + t;
        int j = idx >> 7, h = idx & 127;
        tab[j*129 + h] = AJb[j*HH + h];
    }
    // aiT[h=c128][ii] for this half's 8 i's
    const float* AIb = g_AI + rowbase*HH;
    #pragma unroll
    for (int k = 0; k < 8; ++k)
        hsb[c128*16 + half*8 + k] = AIb[(half*8 + k)*HH + c128];

    int cnt = __syncthreads_count(msk[c128] != 0);
    float sa = (cnt > 0) ? 1.0f : 0.0f;
    bool mj = msk[c128] != 0;

    // ---- PASS 1: logits; thread = (j=c128, half: 8 i's) ----
    float l[8];
    #pragma unroll
    for (int k = 0; k < 8; ++k) l[k] = 0.f;
    {
        const float* tp = tab + c128*129;
        const float* sp = hsb + half*8;
        #pragma unroll 4
        for (int h = 0; h < HH; ++h) {
            float av  = tp[h];
            float a2v = a2s[h];
            float4 s0 = *(const float4*)(sp + h*16);       // broadcast LDS.128
            float4 s1 = *(const float4*)(sp + h*16 + 4);
            l[0] = fmaf(fmaxf(av + s0.x, 0.f), a2v, l[0]);
            l[1] = fmaf(fmaxf(av + s0.y, 0.f), a2v, l[1]);
            l[2] = fmaf(fmaxf(av + s0.z, 0.f), a2v, l[2]);
            l[3] = fmaf(fmaxf(av + s0.w, 0.f), a2v, l[3]);
            l[4] = fmaf(fmaxf(av + s1.x, 0.f), a2v, l[4]);
            l[5] = fmaf(fmaxf(av + s1.y, 0.f), a2v, l[5]);
            l[6] = fmaf(fmaxf(av + s1.z, 0.f), a2v, l[6]);
            l[7] = fmaf(fmaxf(av + s1.w, 0.f), a2v, l[7]);
        }
    }
    if (!mj) {
        #pragma unroll
        for (int k = 0; k < 8; ++k) l[k] = -1e30f;
    }
    // reduce over j within each half (4 warps cover 128 j)
    {
        #pragma unroll
        for (int k = 0; k < 8; ++k) {
            float v = l[k];
            #pragma unroll
            for (int off = 16; off; off >>= 1) v = fmaxf(v, __shfl_xor_sync(0xffffffffu, v, off));
            if (lane == 0) red[half*32 + wq*8 + k] = v;
        }
    }
    __syncthreads();
    float e[8];
    {
        const float* rb = red + half*32;
        #pragma unroll
        for (int k = 0; k < 8; ++k) {
            float mm = fmaxf(fmaxf(rb[k], rb[8+k]), fmaxf(rb[16+k], rb[24+k]));
            e[k] = mj ? __expf(l[k] - mm) : 0.f;
        }
        #pragma unroll
        for (int k = 0; k < 8; ++k) {
            float v = e[k];
            #pragma unroll
            for (int off = 16; off; off >>= 1) v += __shfl_xor_sync(0xffffffffu, v, off);
            if (lane == 0) red[64 + half*32 + wq*8 + k] = v;
        }
    }
    __syncthreads();
    {
        const float* rb = red + 64 + half*32;
        #pragma unroll
        for (int k = 0; k < 8; ++k) {
            float ss = rb[k] + rb[8+k] + rb[16+k] + rb[24+k];
            float inv = (cnt > 0) ? (1.0f / ss) : 0.f;
            attn[c128*16 + half*8 + k] = e[k] * inv;
        }
    }
    __syncthreads();   // attn done; pass1 table reads done

    // ---- reload table with WJ ----
    const float* WJb = g_WJ + b*NN*HH;
    #pragma unroll 8
    for (int it = 0; it < 64; ++it) {
        int idx = it*256 + t;
        int j = idx >> 7, h = idx & 127;
        tab[j*129 + h] = WJb[j*HH + h];
    }
    __syncthreads();

    // ---- PASS 2: weighted hidden sum; thread = (h=c128, half: 8 i's) ----
    {
        const float* WIb = g_WI + rowbase*HH;
        float wi[8], hc[8];
        #pragma unroll
        for (int k = 0; k < 8; ++k) {
            wi[k] = WIb[(half*8 + k)*HH + c128];
            hc[k] = 0.f;
        }
        const float* tp = tab + c128;
        const float* ap = attn + half*8;
        #pragma unroll 4
        for (int j = 0; j < NN; ++j) {
            float wv = tp[j*129];                           // conflict-free scalar
            float4 a0 = *(const float4*)(ap + j*16);        // broadcast LDS.128
            float4 a1 = *(const float4*)(ap + j*16 + 4);
            hc[0] = fmaf(a0.x, fmaxf(wi[0] + wv, 0.f), hc[0]);
            hc[1] = fmaf(a0.y, fmaxf(wi[1] + wv, 0.f), hc[1]);
            hc[2] = fmaf(a0.z, fmaxf(wi[2] + wv, 0.f), hc[2]);
            hc[3] = fmaf(a0.w, fmaxf(wi[3] + wv, 0.f), hc[3]);
            hc[4] = fmaf(a1.x, fmaxf(wi[4] + wv, 0.f), hc[4]);
            hc[5] = fmaf(a1.y, fmaxf(wi[5] + wv, 0.f), hc[5]);
            hc[6] = fmaf(a1.z, fmaxf(wi[6] + wv, 0.f), hc[6]);
            hc[7] = fmaf(a1.w, fmaxf(wi[7] + wv, 0.f), hc[7]);
        }
        #pragma unroll
        for (int k = 0; k < 8; ++k) hsb[(half*8 + k)*128 + c128] = hc[k];
    }
    __syncthreads();   // hs complete; tab free

    // ---- UPDATE phases (overlay xr/aggs/us onto tab) ----
    float* xr   = tab;          // 1024 floats [r=16][64]
    float* aggs = tab + 1024;   // 2048 floats [r][128]
    float* us   = tab + 3072;   // 2048 floats [r][128]

    #pragma unroll
    for (int k = 0; k < 4; ++k) xr[k*256 + t] = xreg[k];

    // Phase A: agg[r][col] = hs[r] @ W2[:,col] + b2[col]*sa   (8 rows/thread)
    {
        float b2v = b2[c128];
        float acc[8];
        #pragma unroll
        for (int k = 0; k < 8; ++k) acc[k] = b2v * sa;
        const float4* hs4 = (const float4*)hsb;
        #pragma unroll 4
        for (int h4 = 0; h4 < 32; ++h4) {
            float wx = W2[(h4*4+0)*HH + c128];
            float wy = W2[(h4*4+1)*HH + c128];
            float wz = W2[(h4*4+2)*HH + c128];
            float ww = W2[(h4*4+3)*HH + c128];
            #pragma unroll
            for (int k = 0; k < 8; ++k) {
                float4 hv = hs4[(half*8 + k)*32 + h4];   // broadcast LDS
                acc[k] += hv.x*wx + hv.y*wy + hv.z*wz + hv.w*ww;
            }
        }
        #pragma unroll
        for (int k = 0; k < 8; ++k) aggs[(half*8 + k)*128 + c128] = acc[k];
    }
    __syncthreads();

    // Phase B: us[r][col] = relu([x_r, agg_r] @ U1[:,col] + ub1[col])
    {
        float ubv = ub1[c128];
        float u[8];
        #pragma unroll
        for (int k = 0; k < 8; ++k) u[k] = ubv;
        const float4* xr4 = (const float4*)xr;
        const float4* ag4 = (const float4*)aggs;
        #pragma unroll 4
        for (int c4 = 0; c4 < 48; ++c4) {
            float wx = U1[(c4*4+0)*HH + c128];
            float wy = U1[(c4*4+1)*HH + c128];
            float wz = U1[(c4*4+2)*HH + c128];
            float ww = U1[(c4*4+3)*HH + c128];
            #pragma unroll
            for (int k = 0; k < 8; ++k) {
                int r = half*8 + k;
                float4 cv = (c4 < 16) ? xr4[r*16 + c4] : ag4[r*32 + (c4-16)];
                u[k] += cv.x*wx + cv.y*wy + cv.z*wz + cv.w*ww;
            }
        }
        #pragma unroll
        for (int k = 0; k < 8; ++k) us[(half*8 + k)*128 + c128] = fmaxf(u[k], 0.f);
    }
    __syncthreads();

    // Phase C: out[r][col] = x[r][col] + us[r] @ U2[:,col] + ub2[col]  (4 rows/thread)
    {
        int col = t & 63;
        int rg  = t >> 6;            // 0..3 -> rows rg*4 .. rg*4+3
        float ub2v = ub2[col];
        float o[4];
        #pragma unroll
        for (int k = 0; k < 4; ++k) o[k] = ub2v;
        const float4* us4 = (const float4*)us;
        #pragma unroll 4
        for (int k4 = 0; k4 < 32; ++k4) {
            float wx = U2[(k4*4+0)*DD + col];
            float wy = U2[(k4*4+1)*DD + col];
            float wz = U2[(k4*4+2)*DD + col];
            float ww = U2[(k4*4+3)*DD + col];
            #pragma unroll
            for (int k = 0; k < 4; ++k) {
                float4 uv = us4[(rg*4 + k)*32 + k4];   // broadcast
                o[k] += uv.x*wx + uv.y*wy + uv.z*wz + uv.w*ww;
            }
        }
        #pragma unroll
        for (int k = 0; k < 4; ++k) {
            int r = rg*4 + k;
            out[(rowbase + r)*DD + col] = xr[r*64 + col] + o[k];
        }
    }
}

// ---------------- launch ----------------
extern "C" void kernel_launch(void* const* d_in, const int* in_sizes, int n_in,
                              void* d_out, int out_size) {
    const float* x    = (const float*)d_in[0];
    const int*   masks= (const int*)  d_in[1];
    const float* W1   = (const float*)d_in[2];
    const float* b1   = (const float*)d_in[3];
    const float* W2   = (const float*)d_in[4];
    const float* b2   = (const float*)d_in[5];
    const float* A1   = (const float*)d_in[6];
    const float* ab1  = (const float*)d_in[7];
    const float* A2   = (const float*)d_in[8];
    // d_in[9] = ab2: cancels in softmax
    const float* U1   = (const float*)d_in[10];
    const float* ub1  = (const float*)d_in[11];
    const float* U2   = (const float*)d_in[12];
    const float* ub2  = (const float*)d_in[13];
    float* out = (float*)d_out;

    cudaFuncSetAttribute(fused_kernel, cudaFuncAttributeMaxDynamicSharedMemorySize, SMEM_FUSED);

    proj_kernel<<<NROWS/16, 256>>>(x, A1, W1, b1, ab1);
    fused_kernel<<<BB*8, 256, SMEM_FUSED>>>(x, A2, masks, W2, b2, U1, ub1, U2, ub2, out);
}